// round 12
// baseline (speedup 1.0000x reference)
#include <cuda_runtime.h>

// ChamferLoss: B=4, N=M=8192, D=3
// Fused symmetric tiles: block computes a (1024 query x 64 candidate) dist tile
// once; emits row-min partials (p1->p2) and col-min partials (p2->p1).
// dist = a^2 + b^2 - 2 a.b via f32x2 packed FMA. Small tiles (4096 jobs) so
// wave quantization over 888 resident CTA slots averages out (~8% tail).

#define TPB     128
#define QPT     8
#define NPTS    8192
#define NB      4
#define QPB     (TPB * QPT)         // 1024 queries per block
#define QCH     (NPTS / QPB)        // 8 query chunks
#define CCH     128                 // candidate chunks
#define CANDS   (NPTS / CCH)        // 64 candidates per block
#define PAIRS   (CANDS / 2)         // 32
#define NSLOT   (NB * NPTS)         // 32768 (b, point) slots
#define F1BLK   64

__device__ float g_row[CCH][NSLOT];   // row-min partial per candidate-chunk (16.8MB)
__device__ float g_col[QCH][NSLOT];   // col-min partial per query-chunk
__device__ float g_part[F1BLK];

typedef unsigned long long u64;

__device__ __forceinline__ u64 ffma2(u64 a, u64 b, u64 c) {
    u64 d;
    asm("fma.rn.f32x2 %0, %1, %2, %3;" : "=l"(d) : "l"(a), "l"(b), "l"(c));
    return d;
}
__device__ __forceinline__ u64 fadd2(u64 a, u64 b) {
    u64 d;
    asm("add.rn.f32x2 %0, %1, %2;" : "=l"(d) : "l"(a), "l"(b));
    return d;
}
__device__ __forceinline__ u64 pack2(float lo, float hi) {
    u64 d;
    asm("mov.b64 %0, {%1, %2};" : "=l"(d) : "f"(lo), "f"(hi));
    return d;
}
__device__ __forceinline__ void unpack2(u64 v, float& lo, float& hi) {
    asm("mov.b64 {%0, %1}, %2;" : "=f"(lo), "=f"(hi) : "l"(v));
}

__global__ __launch_bounds__(TPB, 6) void chamfer_tile_kernel(
    const float* __restrict__ p1, const float* __restrict__ p2)
{
    const int qc = blockIdx.x;            // query chunk (8)
    const int b  = blockIdx.y;            // batch (4)
    const int cc = blockIdx.z;            // candidate chunk (128)
    const float* __restrict__ q = p1 + (size_t)b * NPTS * 3;
    const float* __restrict__ d = p2 + (size_t)b * NPTS * 3 + (size_t)cc * CANDS * 3;

    const int tid  = threadIdx.x;
    const int lane = tid & 31;
    const int w    = tid >> 5;
    const int qbase = qc * QPB;
    const int cbase = cc * CANDS;

    // candidate tile, pair-interleaved packed:
    //  sA[j] = (x_{2j}|x_{2j+1}, y_{2j}|y_{2j+1})
    //  sB[j] = (z_{2j}|z_{2j+1}, b2_{2j}|b2_{2j+1})
    __shared__ ulonglong2 sA[PAIRS];
    __shared__ ulonglong2 sB[PAIRS];
    __shared__ float col_lo[4][PAIRS];    // per-warp col mins (even candidate)
    __shared__ float col_hi[4][PAIRS];    // per-warp col mins (odd candidate)

    if (tid < PAIRS) {   // one pair per thread
        const float* src = d + 6 * tid;
        const float2 f0 = *(const float2*)(src + 0);   // x0 y0
        const float2 f1 = *(const float2*)(src + 2);   // z0 x1
        const float2 f2 = *(const float2*)(src + 4);   // y1 z1
        const float w0 = f0.x * f0.x + f0.y * f0.y + f1.x * f1.x;
        const float w1 = f1.y * f1.y + f2.x * f2.x + f2.y * f2.y;
        sA[tid] = make_ulonglong2(pack2(f0.x, f1.y), pack2(f0.y, f2.x));
        sB[tid] = make_ulonglong2(pack2(f1.x, f2.y), pack2(w0, w1));
    }
    // init col mins: 4*32 = 128 slots == TPB
    ((float*)col_lo)[tid] = 3.4e38f;
    ((float*)col_hi)[tid] = 3.4e38f;

    // 8 query points per thread; coeffs packed (duplicated halves)
    u64 cx[QPT], cy[QPT], cz[QPT], a2p[QPT];
    #pragma unroll
    for (int k = 0; k < QPT; ++k) {
        const int i = qbase + k * TPB + tid;
        const float ax = q[3 * i + 0], ay = q[3 * i + 1], az = q[3 * i + 2];
        const float a2 = ax * ax + ay * ay + az * az;
        cx[k] = pack2(-2.0f * ax, -2.0f * ax);
        cy[k] = pack2(-2.0f * ay, -2.0f * ay);
        cz[k] = pack2(-2.0f * az, -2.0f * az);
        a2p[k] = pack2(a2, a2);
    }
    __syncthreads();

    float be[QPT], bo[QPT];
    #pragma unroll
    for (int k = 0; k < QPT; ++k) { be[k] = 3.4e38f; bo[k] = 3.4e38f; }

    // rotation: at round r, lane l handles pair (l+r)&31 -> all lanes in a warp
    // hit distinct pairs, so per-warp col RMW is race-free without sync.
    #pragma unroll 4
    for (int r = 0; r < PAIRS; ++r) {
        const int j = (lane + r) & (PAIRS - 1);
        const ulonglong2 A  = sA[j];    // (xx, yy)
        const ulonglong2 Bv = sB[j];    // (zz, ww)

        u64 dd[QPT];
        #pragma unroll
        for (int k = 0; k < QPT; ++k) dd[k] = ffma2(cz[k], Bv.x, Bv.y);
        #pragma unroll
        for (int k = 0; k < QPT; ++k) dd[k] = ffma2(cy[k], A.y, dd[k]);
        #pragma unroll
        for (int k = 0; k < QPT; ++k) dd[k] = ffma2(cx[k], A.x, dd[k]);
        #pragma unroll
        for (int k = 0; k < QPT; ++k) dd[k] = fadd2(dd[k], a2p[k]);  // full dist

        float lo[QPT], hi[QPT];
        #pragma unroll
        for (int k = 0; k < QPT; ++k) {
            unpack2(dd[k], lo[k], hi[k]);
            be[k] = fminf(be[k], lo[k]);
            bo[k] = fminf(bo[k], hi[k]);
        }
        // col mins: tree over this thread's 8 queries, then per-warp RMW
        float cE = fminf(fminf(fminf(lo[0], lo[1]), fminf(lo[2], lo[3])),
                         fminf(fminf(lo[4], lo[5]), fminf(lo[6], lo[7])));
        float cO = fminf(fminf(fminf(hi[0], hi[1]), fminf(hi[2], hi[3])),
                         fminf(fminf(hi[4], hi[5]), fminf(hi[6], hi[7])));
        col_lo[w][j] = fminf(col_lo[w][j], cE);
        col_hi[w][j] = fminf(col_hi[w][j], cO);
    }

    // row partials (dist already includes a^2)
    {
        float* dst = &g_row[cc][b * NPTS + qbase];
        #pragma unroll
        for (int k = 0; k < QPT; ++k)
            dst[k * TPB + tid] = fminf(be[k], bo[k]);
    }

    // col partials: combine 4 warp copies
    __syncthreads();
    if (tid < PAIRS) {
        const int p = tid;
        const float mE = fminf(fminf(col_lo[0][p], col_lo[1][p]),
                               fminf(col_lo[2][p], col_lo[3][p]));
        const float mO = fminf(fminf(col_hi[0][p], col_hi[1][p]),
                               fminf(col_hi[2][p], col_hi[3][p]));
        float* dst = &g_col[qc][b * NPTS + cbase];
        dst[2 * p + 0] = mE;
        dst[2 * p + 1] = mO;
    }
}

__global__ __launch_bounds__(256) void chamfer_finalize1(void)
{
    __shared__ float red[8];
    const int t = blockIdx.x * 256 + threadIdx.x;   // 16384 threads
    float s = 0.0f;
    #pragma unroll
    for (int r = 0; r < NSLOT / 16384; ++r) {       // 2 slots per thread
        const int f = t + r * 16384;
        float m = g_row[0][f];
        #pragma unroll 8
        for (int c = 1; c < CCH; ++c) m = fminf(m, g_row[c][f]);
        s += m;
        float m2 = g_col[0][f];
        #pragma unroll
        for (int c = 1; c < QCH; ++c) m2 = fminf(m2, g_col[c][f]);
        s += m2;
    }
    #pragma unroll
    for (int o = 16; o > 0; o >>= 1)
        s += __shfl_down_sync(0xffffffffu, s, o);
    if ((threadIdx.x & 31) == 0) red[threadIdx.x >> 5] = s;
    __syncthreads();
    if (threadIdx.x < 8) {
        s = red[threadIdx.x];
        #pragma unroll
        for (int o = 4; o > 0; o >>= 1)
            s += __shfl_down_sync(0xffu, s, o);
        if (threadIdx.x == 0) g_part[blockIdx.x] = s;
    }
}

__global__ void chamfer_finalize2(float* __restrict__ out)
{
    __shared__ float red[2];
    float v = g_part[threadIdx.x];   // 64 threads
    #pragma unroll
    for (int o = 16; o > 0; o >>= 1)
        v += __shfl_down_sync(0xffffffffu, v, o);
    if ((threadIdx.x & 31) == 0) red[threadIdx.x >> 5] = v;
    __syncthreads();
    if (threadIdx.x == 0)
        out[0] = (red[0] + red[1]) * (1.0f / (float)(NB * NPTS));
}

extern "C" void kernel_launch(void* const* d_in, const int* in_sizes, int n_in,
                              void* d_out, int out_size)
{
    const float* p1 = (const float*)d_in[0];
    const float* p2 = (const float*)d_in[1];
    float* out = (float*)d_out;

    dim3 grid(QCH, NB, CCH);   // 8 x 4 x 128 = 4096 blocks
    chamfer_tile_kernel<<<grid, TPB>>>(p1, p2);
    chamfer_finalize1<<<F1BLK, 256>>>();
    chamfer_finalize2<<<1, F1BLK>>>(out);
}

// round 13
// speedup vs baseline: 1.1571x; 1.1571x over previous
#include <cuda_runtime.h>

// ChamferLoss: B=4, N=M=8192, D=3
// Fused symmetric tiles: block computes a (1024 query x 256 candidate) dist
// tile once; emits row-min partials (p1->p2) and col-min partials (p2->p1).
// dist = a^2 + b^2 - 2 a.b via f32x2 packed FMA. Tile LDS software-pipelined
// to hide shared-memory latency behind the FMA-pipe-bound compute block.

#define TPB     128
#define QPT     8
#define NPTS    8192
#define NB      4
#define QPB     (TPB * QPT)         // 1024 queries per block
#define QCH     (NPTS / QPB)        // 8 query chunks
#define CCH     32                  // candidate chunks
#define CANDS   (NPTS / CCH)        // 256 candidates per block
#define PAIRS   (CANDS / 2)         // 128 == TPB
#define NSLOT   (NB * NPTS)         // 32768 (b, point) slots
#define F1BLK   64

__device__ float g_row[CCH][NSLOT];   // row-min partial per candidate-chunk
__device__ float g_col[QCH][NSLOT];   // col-min partial per query-chunk
__device__ float g_part[F1BLK];

typedef unsigned long long u64;

__device__ __forceinline__ u64 ffma2(u64 a, u64 b, u64 c) {
    u64 d;
    asm("fma.rn.f32x2 %0, %1, %2, %3;" : "=l"(d) : "l"(a), "l"(b), "l"(c));
    return d;
}
__device__ __forceinline__ u64 fadd2(u64 a, u64 b) {
    u64 d;
    asm("add.rn.f32x2 %0, %1, %2;" : "=l"(d) : "l"(a), "l"(b));
    return d;
}
__device__ __forceinline__ u64 pack2(float lo, float hi) {
    u64 d;
    asm("mov.b64 %0, {%1, %2};" : "=l"(d) : "f"(lo), "f"(hi));
    return d;
}
__device__ __forceinline__ void unpack2(u64 v, float& lo, float& hi) {
    asm("mov.b64 {%0, %1}, %2;" : "=f"(lo), "=f"(hi) : "l"(v));
}

__global__ __launch_bounds__(TPB) void chamfer_tile_kernel(
    const float* __restrict__ p1, const float* __restrict__ p2)
{
    const int qc = blockIdx.x;            // query chunk (8)
    const int b  = blockIdx.y;            // batch (4)
    const int cc = blockIdx.z;            // candidate chunk (32)
    const float* __restrict__ q = p1 + (size_t)b * NPTS * 3;
    const float* __restrict__ d = p2 + (size_t)b * NPTS * 3 + (size_t)cc * CANDS * 3;

    const int tid  = threadIdx.x;
    const int lane = tid & 31;
    const int w    = tid >> 5;
    const int qbase = qc * QPB;
    const int cbase = cc * CANDS;

    // candidate tile, pair-interleaved packed:
    //  sA[j] = (x_{2j}|x_{2j+1}, y_{2j}|y_{2j+1})
    //  sB[j] = (z_{2j}|z_{2j+1}, b2_{2j}|b2_{2j+1})
    __shared__ ulonglong2 sA[PAIRS];
    __shared__ ulonglong2 sB[PAIRS];
    __shared__ float col_lo[4][PAIRS];    // per-warp col mins (even candidate)
    __shared__ float col_hi[4][PAIRS];    // per-warp col mins (odd candidate)

    {   // one pair per thread (PAIRS == TPB)
        const float* src = d + 6 * tid;
        const float2 f0 = *(const float2*)(src + 0);   // x0 y0
        const float2 f1 = *(const float2*)(src + 2);   // z0 x1
        const float2 f2 = *(const float2*)(src + 4);   // y1 z1
        const float w0 = f0.x * f0.x + f0.y * f0.y + f1.x * f1.x;
        const float w1 = f1.y * f1.y + f2.x * f2.x + f2.y * f2.y;
        sA[tid] = make_ulonglong2(pack2(f0.x, f1.y), pack2(f0.y, f2.x));
        sB[tid] = make_ulonglong2(pack2(f1.x, f2.y), pack2(w0, w1));
    }
    #pragma unroll
    for (int ww = 0; ww < 4; ++ww) {
        col_lo[ww][tid] = 3.4e38f;
        col_hi[ww][tid] = 3.4e38f;
    }

    // 8 query points per thread; coeffs packed (duplicated halves)
    u64 cx[QPT], cy[QPT], cz[QPT], a2p[QPT];
    #pragma unroll
    for (int k = 0; k < QPT; ++k) {
        const int i = qbase + k * TPB + tid;
        const float ax = q[3 * i + 0], ay = q[3 * i + 1], az = q[3 * i + 2];
        const float a2 = ax * ax + ay * ay + az * az;
        cx[k] = pack2(-2.0f * ax, -2.0f * ax);
        cy[k] = pack2(-2.0f * ay, -2.0f * ay);
        cz[k] = pack2(-2.0f * az, -2.0f * az);
        a2p[k] = pack2(a2, a2);
    }
    __syncthreads();

    float be[QPT], bo[QPT];
    #pragma unroll
    for (int k = 0; k < QPT; ++k) { be[k] = 3.4e38f; bo[k] = 3.4e38f; }

    // rotation: at round r, lane l handles pair (l+r)&127 -> all lanes in a
    // warp hit distinct pairs, so per-warp col RMW is race-free without sync.
    // Software pipeline: prefetch round r+1's tile entry during round r.
    int j = lane;
    ulonglong2 A  = sA[j];
    ulonglong2 Bv = sB[j];

    #pragma unroll 2
    for (int r = 0; r < PAIRS; ++r) {
        const int jn = (j + 1) & (PAIRS - 1);
        const ulonglong2 An  = sA[jn];      // prefetch (wraps harmlessly on last)
        const ulonglong2 Bn  = sB[jn];

        u64 dd[QPT];
        #pragma unroll
        for (int k = 0; k < QPT; ++k) dd[k] = ffma2(cz[k], Bv.x, Bv.y);
        #pragma unroll
        for (int k = 0; k < QPT; ++k) dd[k] = ffma2(cy[k], A.y, dd[k]);
        #pragma unroll
        for (int k = 0; k < QPT; ++k) dd[k] = ffma2(cx[k], A.x, dd[k]);
        #pragma unroll
        for (int k = 0; k < QPT; ++k) dd[k] = fadd2(dd[k], a2p[k]);  // full dist

        float lo[QPT], hi[QPT];
        #pragma unroll
        for (int k = 0; k < QPT; ++k) {
            unpack2(dd[k], lo[k], hi[k]);
            be[k] = fminf(be[k], lo[k]);
            bo[k] = fminf(bo[k], hi[k]);
        }
        // col mins: tree over this thread's 8 queries, then per-warp RMW
        float cE = fminf(fminf(fminf(lo[0], lo[1]), fminf(lo[2], lo[3])),
                         fminf(fminf(lo[4], lo[5]), fminf(lo[6], lo[7])));
        float cO = fminf(fminf(fminf(hi[0], hi[1]), fminf(hi[2], hi[3])),
                         fminf(fminf(hi[4], hi[5]), fminf(hi[6], hi[7])));
        col_lo[w][j] = fminf(col_lo[w][j], cE);
        col_hi[w][j] = fminf(col_hi[w][j], cO);

        A = An; Bv = Bn; j = jn;
    }

    // row partials (dist already includes a^2)
    {
        float* dst = &g_row[cc][b * NPTS + qbase];
        #pragma unroll
        for (int k = 0; k < QPT; ++k)
            dst[k * TPB + tid] = fminf(be[k], bo[k]);
    }

    // col partials: combine 4 warp copies
    __syncthreads();
    {
        const int p = tid;   // PAIRS == TPB
        const float mE = fminf(fminf(col_lo[0][p], col_lo[1][p]),
                               fminf(col_lo[2][p], col_lo[3][p]));
        const float mO = fminf(fminf(col_hi[0][p], col_hi[1][p]),
                               fminf(col_hi[2][p], col_hi[3][p]));
        float* dst = &g_col[qc][b * NPTS + cbase];
        dst[2 * p + 0] = mE;
        dst[2 * p + 1] = mO;
    }
}

__global__ __launch_bounds__(256) void chamfer_finalize1(void)
{
    __shared__ float red[8];
    const int t = blockIdx.x * 256 + threadIdx.x;   // 16384 threads
    float s = 0.0f;
    #pragma unroll
    for (int r = 0; r < NSLOT / 16384; ++r) {       // 2 row + 2 col slots/thread
        const int f = t + r * 16384;
        float m = g_row[0][f];
        #pragma unroll
        for (int c = 1; c < CCH; ++c) m = fminf(m, g_row[c][f]);
        s += m;
        float m2 = g_col[0][f];
        #pragma unroll
        for (int c = 1; c < QCH; ++c) m2 = fminf(m2, g_col[c][f]);
        s += m2;
    }
    #pragma unroll
    for (int o = 16; o > 0; o >>= 1)
        s += __shfl_down_sync(0xffffffffu, s, o);
    if ((threadIdx.x & 31) == 0) red[threadIdx.x >> 5] = s;
    __syncthreads();
    if (threadIdx.x < 8) {
        s = red[threadIdx.x];
        #pragma unroll
        for (int o = 4; o > 0; o >>= 1)
            s += __shfl_down_sync(0xffu, s, o);
        if (threadIdx.x == 0) g_part[blockIdx.x] = s;
    }
}

__global__ void chamfer_finalize2(float* __restrict__ out)
{
    __shared__ float red[2];
    float v = g_part[threadIdx.x];   // 64 threads
    #pragma unroll
    for (int o = 16; o > 0; o >>= 1)
        v += __shfl_down_sync(0xffffffffu, v, o);
    if ((threadIdx.x & 31) == 0) red[threadIdx.x >> 5] = v;
    __syncthreads();
    if (threadIdx.x == 0)
        out[0] = (red[0] + red[1]) * (1.0f / (float)(NB * NPTS));
}

extern "C" void kernel_launch(void* const* d_in, const int* in_sizes, int n_in,
                              void* d_out, int out_size)
{
    const float* p1 = (const float*)d_in[0];
    const float* p2 = (const float*)d_in[1];
    float* out = (float*)d_out;

    dim3 grid(QCH, NB, CCH);   // 8 x 4 x 32 = 1024 blocks
    chamfer_tile_kernel<<<grid, TPB>>>(p1, p2);
    chamfer_finalize1<<<F1BLK, 256>>>();
    chamfer_finalize2<<<1, F1BLK>>>(out);
}